// round 3
// baseline (speedup 1.0000x reference)
#include <cuda_runtime.h>
#include <cuda_fp16.h>
#include <cstdint>

#define N_NODES 100000
#define N_EDGES 1600000
#define E_TOT   (N_EDGES + N_NODES)   // self loops appended
#define N_GRAPHS 1024
#define EPS_BN 1e-5f
#define SCAN_B 98                      // ceil(N_NODES / 1024)

// ----------------------------- scratch (device globals) -----------------------------
__device__ int    g_is64;
__device__ int    g_src[E_TOT];
__device__ int    g_dst[E_TOT];
__device__ int    g_batch[N_NODES];
__device__ int    g_deg[N_NODES];
__device__ int    g_off[N_NODES + 1];
__device__ int    g_cur[N_NODES];
__device__ int    g_csr[E_TOT];
__device__ int    g_bsum[SCAN_B];
__device__ __half g_hlinh[N_NODES * 128];  // post-GEMM features, fp16 (attn gather input)
__device__ float  g_feat[N_NODES * 128];   // attn output (raw, pre-BN) / GEMM input
__device__ float  g_als[N_NODES * 4];
__device__ float  g_ald[N_NODES * 4];
__device__ float  g_bnsum[256];            // [0:128) sum, [128:256) sumsq
__device__ float  g_pool[N_GRAPHS * 128];  // mean (0..63) || max (64..127)

// ----------------------------- utility -----------------------------
__device__ __forceinline__ float eluf(float v) { return v > 0.f ? v : expm1f(v); }

__device__ __forceinline__ unsigned long long pack2(float x, float y) {
    unsigned long long r;
    asm("mov.b64 %0, {%1, %2};" : "=l"(r) : "f"(x), "f"(y));
    return r;
}
__device__ __forceinline__ float2 unpack2(unsigned long long v) {
    float2 r;
    asm("mov.b64 {%0, %1}, %2;" : "=f"(r.x), "=f"(r.y) : "l"(v));
    return r;
}
#define FMA_F32X2(acc, a, b) \
    asm("fma.rn.f32x2 %0, %1, %2, %0;" : "+l"(acc) : "l"(a), "l"(b))

// ----------------------------- dtype detection -----------------------------
__global__ void detect_kernel(const void* ei) {
    __shared__ int any;
    if (threadIdx.x == 0) any = 0;
    __syncthreads();
    const int* p = (const int*)ei;
    int local = 0;
    for (int i = threadIdx.x; i < 2048; i += 256)
        if (p[2 * i + 1] != 0) local = 1;
    if (local) atomicOr(&any, 1);
    __syncthreads();
    if (threadIdx.x == 0) g_is64 = any ? 0 : 1;
}

__global__ void zero_deg_kernel() {
    int i = blockIdx.x * 256 + threadIdx.x;
    if (i < N_NODES) g_deg[i] = 0;
}

__global__ void convert_kernel(const void* ei, const void* batch) {
    int i = blockIdx.x * 256 + threadIdx.x;
    int is64 = g_is64;
    if (i < E_TOT) {
        int s, d;
        if (i < N_EDGES) {
            if (is64) {
                s = (int)((const long long*)ei)[i];
                d = (int)((const long long*)ei)[N_EDGES + i];
            } else {
                s = ((const int*)ei)[i];
                d = ((const int*)ei)[N_EDGES + i];
            }
        } else {
            s = d = i - N_EDGES;
        }
        g_src[i] = s;
        g_dst[i] = d;
        atomicAdd(&g_deg[d], 1);
    }
    if (i < N_NODES) {
        g_batch[i] = is64 ? (int)((const long long*)batch)[i] : ((const int*)batch)[i];
    }
}

// ----------------------------- hierarchical exclusive scan -----------------------------
__global__ void scan_partial_kernel() {
    __shared__ int sh[512];
    int t = threadIdx.x;
    int base = blockIdx.x * 1024;
    int i0 = base + t, i1 = base + 512 + t;
    int v = ((i0 < N_NODES) ? g_deg[i0] : 0) + ((i1 < N_NODES) ? g_deg[i1] : 0);
    sh[t] = v;
    __syncthreads();
    for (int o = 256; o; o >>= 1) {
        if (t < o) sh[t] += sh[t + o];
        __syncthreads();
    }
    if (t == 0) g_bsum[blockIdx.x] = sh[0];
}

__global__ void scan_mid_kernel() {
    __shared__ int sh[128];
    int t = threadIdx.x;
    int orig = (t < SCAN_B) ? g_bsum[t] : 0;
    sh[t] = orig;
    __syncthreads();
    for (int o = 1; o < 128; o <<= 1) {
        int v = (t >= o) ? sh[t - o] : 0;
        __syncthreads();
        sh[t] += v;
        __syncthreads();
    }
    if (t < SCAN_B) g_bsum[t] = sh[t] - orig;
    if (t == 0) g_off[N_NODES] = E_TOT;
}

__global__ void scan_final_kernel() {
    __shared__ int wsum[16];
    int t = threadIdx.x;
    int base = blockIdx.x * 1024;
    int i0 = base + 2 * t, i1 = i0 + 1;
    int d0 = (i0 < N_NODES) ? g_deg[i0] : 0;
    int d1 = (i1 < N_NODES) ? g_deg[i1] : 0;
    int tsum = d0 + d1;
    int lane = t & 31, wid = t >> 5;
    int v = tsum;
#pragma unroll
    for (int o = 1; o < 32; o <<= 1) {
        int u = __shfl_up_sync(0xffffffffu, v, o);
        if (lane >= o) v += u;
    }
    if (lane == 31) wsum[wid] = v;
    __syncthreads();
    if (t < 16) {
        int w = wsum[t];
#pragma unroll
        for (int o = 1; o < 16; o <<= 1) {
            int u = __shfl_up_sync(0xffffu, w, o);
            if (t >= o) w += u;
        }
        wsum[t] = w;
    }
    __syncthreads();
    int excl = v - tsum + (wid ? wsum[wid - 1] : 0) + g_bsum[blockIdx.x];
    if (i0 < N_NODES) { g_off[i0] = excl;      g_cur[i0] = excl; }
    if (i1 < N_NODES) { g_off[i1] = excl + d0; g_cur[i1] = excl + d0; }
}

__global__ void fill_kernel() {
    int i = blockIdx.x * 256 + threadIdx.x;
    if (i < E_TOT) {
        int p = atomicAdd(&g_cur[g_dst[i]], 1);
        g_csr[p] = g_src[i];
    }
}

// ----------------------------- layer-1 GEMM (5 -> 128) + als epilogue -----------------------
// warp per node; lane owns channels [lane*4, lane*4+4)
__global__ void gemm1_kernel(const float* __restrict__ x, const float* __restrict__ W1,
                             const float* __restrict__ aS, const float* __restrict__ aD) {
    int node = blockIdx.x * 8 + (threadIdx.x >> 5);
    int lane = threadIdx.x & 31;
    if (node >= N_NODES) return;
    float acc[4] = {0.f, 0.f, 0.f, 0.f};
    const float* xr = x + node * 5;
#pragma unroll
    for (int k = 0; k < 5; k++) {
        float xv = __ldg(&xr[k]);
        float4 w = __ldg((const float4*)(W1 + k * 128 + lane * 4));
        acc[0] += xv * w.x; acc[1] += xv * w.y; acc[2] += xv * w.z; acc[3] += xv * w.w;
    }
    // store fp16
    __half2 h0 = __floats2half2_rn(acc[0], acc[1]);
    __half2 h1 = __floats2half2_rn(acc[2], acc[3]);
    uint2 st;
    st.x = *(unsigned*)&h0; st.y = *(unsigned*)&h1;
    *(uint2*)(g_hlinh + node * 128 + lane * 4) = st;
    // als/ald: channel base = lane*4 (flat channel == flat a index); head = lane/8
    float pS = 0.f, pD = 0.f;
#pragma unroll
    for (int j = 0; j < 4; j++) {
        pS += acc[j] * __ldg(&aS[lane * 4 + j]);
        pD += acc[j] * __ldg(&aD[lane * 4 + j]);
    }
#pragma unroll
    for (int o = 1; o < 8; o <<= 1) {
        pS += __shfl_xor_sync(0xffffffffu, pS, o);
        pD += __shfl_xor_sync(0xffffffffu, pD, o);
    }
    if ((lane & 7) == 0) {
        int h = lane >> 3;
        g_als[node * 4 + h] = pS;
        g_ald[node * 4 + h] = pD;
    }
}

// ----------------------------- 128 -> OUTC GEMM (FFMA2) + fused BN-in + als epilogue --------
template <int OUTC>
__global__ void gemm_kernel(const float* __restrict__ W,
                            const float* __restrict__ aS, const float* __restrict__ aD,
                            const float* __restrict__ bnG, const float* __restrict__ bnBe) {
    constexpr int CJ2 = OUTC / 64;             // channel-pairs per thread
    __shared__ float As[64][33];
    __shared__ unsigned long long Ws2[32][OUTC / 2];
    __shared__ float sScale[128], sShift[128];
    int t = threadIdx.x;   // 256
    int tc = t & 31;
    int tn = t >> 5;       // warp id = row group
    int nodeBase = blockIdx.x * 64;

    if (t < 128) {
        const float invN = 1.f / (float)N_NODES;
        float mu = g_bnsum[t] * invN;
        float var = g_bnsum[128 + t] * invN - mu * mu;
        float rs = rsqrtf(var + EPS_BN);
        float sc = rs * __ldg(&bnG[t]);
        sScale[t] = sc;
        sShift[t] = __ldg(&bnBe[t]) - mu * sc;
    }

    unsigned long long acc[8][CJ2];
#pragma unroll
    for (int r = 0; r < 8; r++)
#pragma unroll
        for (int cj = 0; cj < CJ2; cj++) acc[r][cj] = 0ull;

    const float2* Wp = (const float2*)W;
    __syncthreads();
    for (int kc = 0; kc < 4; kc++) {
#pragma unroll
        for (int j = 0; j < 8; j++) {
            int idx = t + j * 256;
            int row = idx >> 5, col = idx & 31;
            int node = nodeBase + row;
            int c = kc * 32 + col;
            float v = 0.f;
            if (node < N_NODES)
                v = eluf(g_feat[node * 128 + c] * sScale[c] + sShift[c]);
            As[row][col] = v;
        }
#pragma unroll
        for (int j = 0; j < (32 * OUTC / 2) / 256; j++) {
            int idx = t + j * 256;
            int r = idx / (OUTC / 2), c2 = idx % (OUTC / 2);
            float2 w = __ldg(&Wp[(kc * 32 + r) * (OUTC / 2) + c2]);
            Ws2[r][c2] = pack2(w.x, w.y);
        }
        __syncthreads();
#pragma unroll
        for (int kk = 0; kk < 32; kk++) {
            unsigned long long w[CJ2];
#pragma unroll
            for (int cj = 0; cj < CJ2; cj++) w[cj] = Ws2[kk][tc + 32 * cj];
#pragma unroll
            for (int r = 0; r < 8; r++) {
                float a = As[tn * 8 + r][kk];
                unsigned long long a2 = pack2(a, a);
#pragma unroll
                for (int cj = 0; cj < CJ2; cj++) FMA_F32X2(acc[r][cj], a2, w[cj]);
            }
        }
        __syncthreads();
    }

    // epilogue: fp16 store + als/ald warp reductions (lanes of this warp = tc)
#pragma unroll
    for (int r = 0; r < 8; r++) {
        int node = nodeBase + tn * 8 + r;
        if (node >= N_NODES) continue;
        __half2* outp = (__half2*)(g_hlinh + node * OUTC);
        float2 f[CJ2];
#pragma unroll
        for (int cj = 0; cj < CJ2; cj++) {
            f[cj] = unpack2(acc[r][cj]);
            outp[tc + 32 * cj] = __floats2half2_rn(f[cj].x, f[cj].y);
        }
        if (OUTC == 128) {
            // pair0: channels 2tc,2tc+1 (head tc/16); pair1: channels 64+2tc,.. (head 2+tc/16)
            float pS0 = f[0].x * __ldg(&aS[2 * tc]) + f[0].y * __ldg(&aS[2 * tc + 1]);
            float pD0 = f[0].x * __ldg(&aD[2 * tc]) + f[0].y * __ldg(&aD[2 * tc + 1]);
            float pS1 = f[CJ2 - 1].x * __ldg(&aS[64 + 2 * tc]) + f[CJ2 - 1].y * __ldg(&aS[64 + 2 * tc + 1]);
            float pD1 = f[CJ2 - 1].x * __ldg(&aD[64 + 2 * tc]) + f[CJ2 - 1].y * __ldg(&aD[64 + 2 * tc + 1]);
#pragma unroll
            for (int o = 1; o < 16; o <<= 1) {
                pS0 += __shfl_xor_sync(0xffffffffu, pS0, o);
                pD0 += __shfl_xor_sync(0xffffffffu, pD0, o);
                pS1 += __shfl_xor_sync(0xffffffffu, pS1, o);
                pD1 += __shfl_xor_sync(0xffffffffu, pD1, o);
            }
            if ((tc & 15) == 0) {
                int hg = tc >> 4;   // 0 or 1
                g_als[node * 4 + hg] = pS0;
                g_ald[node * 4 + hg] = pD0;
                g_als[node * 4 + 2 + hg] = pS1;
                g_ald[node * 4 + 2 + hg] = pD1;
            }
        } else {
            // OUTC==64, single head: channels 2tc,2tc+1
            float pS = f[0].x * __ldg(&aS[2 * tc]) + f[0].y * __ldg(&aS[2 * tc + 1]);
            float pD = f[0].x * __ldg(&aD[2 * tc]) + f[0].y * __ldg(&aD[2 * tc + 1]);
#pragma unroll
            for (int o = 1; o < 32; o <<= 1) {
                pS += __shfl_xor_sync(0xffffffffu, pS, o);
                pD += __shfl_xor_sync(0xffffffffu, pD, o);
            }
            if (tc == 0) {
                g_als[node] = pS;
                g_ald[node] = pD;
            }
        }
    }
}

// ----------------------------- GAT aggregation: warp/dst, fp16 gather ------------------------
template <int H, int HC, bool ELU_OUT>
__global__ void attn_kernel(const float* __restrict__ bias) {
    constexpr int K = HC / 32;
    constexpr int C = HC / H;
    int node = (blockIdx.x * blockDim.x + threadIdx.x) >> 5;
    int lane = threadIdx.x & 31;
    if (node >= N_NODES) return;
    const int h0 = (lane * K) / C;

    float ad = g_ald[node * H + h0];
    float m = __int_as_float(0xff800000);
    float s = 0.f;
    float acc[K];
#pragma unroll
    for (int k = 0; k < K; k++) acc[k] = 0.f;

    int beg = g_off[node], end = g_off[node + 1];
#pragma unroll 2
    for (int i = beg; i < end; i++) {
        int src = __ldg(&g_csr[i]);
        float v = __ldg(&g_als[src * H + h0]) + ad;
        float e = v > 0.f ? v : 0.2f * v;
        float hv[K];
        if (K == 4) {
            uint2 q = *(const uint2*)(g_hlinh + src * HC + lane * 4);
            float2 f0 = __half22float2(*(__half2*)&q.x);
            float2 f1 = __half22float2(*(__half2*)&q.y);
            hv[0] = f0.x; hv[1] = f0.y; hv[2] = f1.x; hv[3] = f1.y;
        } else {
            unsigned q = *(const unsigned*)(g_hlinh + src * HC + lane * 2);
            float2 f0 = __half22float2(*(__half2*)&q);
            hv[0] = f0.x; hv[1] = f0.y;
        }
        float newm = fmaxf(m, e);
        float sc = __expf(m - newm);
        float p  = __expf(e - newm);
        s = s * sc + p;
#pragma unroll
        for (int k = 0; k < K; k++) acc[k] = acc[k] * sc + p * hv[k];
        m = newm;
    }

    float inv = 1.f / (s + 1e-16f);
    if (K == 4) {
        float4 o;
        o.x = acc[0] * inv + __ldg(&bias[lane * 4 + 0]);
        o.y = acc[1] * inv + __ldg(&bias[lane * 4 + 1]);
        o.z = acc[2] * inv + __ldg(&bias[lane * 4 + 2]);
        o.w = acc[3] * inv + __ldg(&bias[lane * 4 + 3]);
        if (ELU_OUT) { o.x = eluf(o.x); o.y = eluf(o.y); o.z = eluf(o.z); o.w = eluf(o.w); }
        *(float4*)(g_feat + node * HC + lane * 4) = o;
    } else {
        float2 o;
        o.x = acc[0] * inv + __ldg(&bias[lane * 2 + 0]);
        o.y = acc[1] * inv + __ldg(&bias[lane * 2 + 1]);
        if (ELU_OUT) { o.x = eluf(o.x); o.y = eluf(o.y); }
        *(float2*)(g_feat + node * HC + lane * 2) = o;
    }
}

// ----------------------------- batch norm stats -----------------------------
__global__ void zero_bnsum_kernel() {
    if (threadIdx.x < 256) g_bnsum[threadIdx.x] = 0.f;
}

__global__ void bnstats_kernel() {
    int c = threadIdx.x;  // 128
    int n0 = blockIdx.x * 128;
    float s = 0.f, sq = 0.f;
    for (int r = 0; r < 128; r++) {
        int n = n0 + r;
        if (n < N_NODES) {
            float v = g_feat[n * 128 + c];
            s += v;
            sq += v * v;
        }
    }
    atomicAdd(&g_bnsum[c], s);
    atomicAdd(&g_bnsum[128 + c], sq);
}

// ----------------------------- pooling (batch sorted) -----------------------------
__device__ __forceinline__ int lower_bound_batch(int key) {
    int lo = 0, hi = N_NODES;
    while (lo < hi) {
        int mid = (lo + hi) >> 1;
        if (g_batch[mid] < key) lo = mid + 1;
        else hi = mid;
    }
    return lo;
}

__global__ void pool_kernel() {
    int gidx = blockIdx.x;
    __shared__ int se[2];
    if (threadIdx.x == 0) se[0] = lower_bound_batch(gidx);
    if (threadIdx.x == 1) se[1] = lower_bound_batch(gidx + 1);
    __syncthreads();
    int beg = se[0], end = se[1];
    int c = threadIdx.x & 63, sl = threadIdx.x >> 6;
    float sum = 0.f, mx = __int_as_float(0xff800000);
    for (int n = beg + sl; n < end; n += 2) {
        float v = g_feat[n * 64 + c];
        sum += v;
        mx = fmaxf(mx, v);
    }
    __shared__ float shs[128], shm[128];
    shs[threadIdx.x] = sum;
    shm[threadIdx.x] = mx;
    __syncthreads();
    if (sl == 0) {
        sum += shs[64 + c];
        mx = fmaxf(mx, shm[64 + c]);
        int cnt = end - beg;
        float mean = (cnt > 0) ? sum / (float)cnt : 0.f;
        float maxv = (cnt > 0) ? mx : 0.f;
        g_pool[gidx * 128 + c] = mean;
        g_pool[gidx * 128 + 64 + c] = maxv;
    }
}

// ----------------------------- classifier -----------------------------
__global__ void final_kernel(const float* __restrict__ fc1w, const float* __restrict__ fc1b,
                             const float* __restrict__ fc2w, const float* __restrict__ fc2b,
                             float* __restrict__ out) {
    int gidx = blockIdx.x;
    int c = threadIdx.x;  // 64
    __shared__ float hg[128];
    hg[c] = g_pool[gidx * 128 + c];
    hg[c + 64] = g_pool[gidx * 128 + 64 + c];
    __syncthreads();
    float acc = __ldg(&fc1b[c]);
#pragma unroll 8
    for (int k = 0; k < 128; k++) acc += hg[k] * __ldg(&fc1w[k * 64 + c]);
    float z = eluf(acc);
    float part = z * __ldg(&fc2w[c]);
#pragma unroll
    for (int off = 16; off; off >>= 1) part += __shfl_xor_sync(0xffffffffu, part, off);
    __shared__ float warpsum[2];
    if ((c & 31) == 0) warpsum[c >> 5] = part;
    __syncthreads();
    if (c == 0) out[gidx] = warpsum[0] + warpsum[1] + __ldg(&fc2b[0]);
}

// ----------------------------- launch -----------------------------
extern "C" void kernel_launch(void* const* d_in, const int* in_sizes, int n_in,
                              void* d_out, int out_size) {
    const float* x      = (const float*)d_in[0];
    const void*  ei     = d_in[1];
    const void*  batch  = d_in[2];
    const float* W1     = (const float*)d_in[3];
    const float* a1_src = (const float*)d_in[4];
    const float* a1_dst = (const float*)d_in[5];
    const float* b1     = (const float*)d_in[6];
    const float* g1     = (const float*)d_in[7];
    const float* be1    = (const float*)d_in[8];
    const float* W2     = (const float*)d_in[9];
    const float* a2_src = (const float*)d_in[10];
    const float* a2_dst = (const float*)d_in[11];
    const float* b2     = (const float*)d_in[12];
    const float* g2     = (const float*)d_in[13];
    const float* be2    = (const float*)d_in[14];
    const float* W3     = (const float*)d_in[15];
    const float* a3_src = (const float*)d_in[16];
    const float* a3_dst = (const float*)d_in[17];
    const float* b3     = (const float*)d_in[18];
    const float* fc1_w  = (const float*)d_in[19];
    const float* fc1_b  = (const float*)d_in[20];
    const float* fc2_w  = (const float*)d_in[21];
    const float* fc2_b  = (const float*)d_in[22];
    float* out = (float*)d_out;

    const int EB = (E_TOT + 255) / 256;
    const int ATTN_B = (N_NODES + 7) / 8;
    const int GEMM_B = (N_NODES + 63) / 64;

    // graph structure (CSR by dst)
    detect_kernel<<<1, 256>>>(ei);
    zero_deg_kernel<<<(N_NODES + 255) / 256, 256>>>();
    convert_kernel<<<EB, 256>>>(ei, batch);
    scan_partial_kernel<<<SCAN_B, 512>>>();
    scan_mid_kernel<<<1, 128>>>();
    scan_final_kernel<<<SCAN_B, 512>>>();
    fill_kernel<<<EB, 256>>>();

    // ---- layer 1: 5 -> 4x32 (als fused in GEMM epilogue) ----
    gemm1_kernel<<<(N_NODES + 7) / 8, 256>>>(x, W1, a1_src, a1_dst);
    attn_kernel<4, 128, false><<<ATTN_B, 256>>>(b1);
    zero_bnsum_kernel<<<1, 256>>>();
    bnstats_kernel<<<(N_NODES + 127) / 128, 128>>>();

    // ---- layer 2: BN1+ELU fused into GEMM A-load; als fused in epilogue ----
    gemm_kernel<128><<<GEMM_B, 256>>>(W2, a2_src, a2_dst, g1, be1);
    attn_kernel<4, 128, false><<<ATTN_B, 256>>>(b2);
    zero_bnsum_kernel<<<1, 256>>>();
    bnstats_kernel<<<(N_NODES + 127) / 128, 128>>>();

    // ---- layer 3: BN2+ELU fused into GEMM A-load; single head; ELU in attn ----
    gemm_kernel<64><<<GEMM_B, 256>>>(W3, a3_src, a3_dst, g2, be2);
    attn_kernel<1, 64, true><<<ATTN_B, 256>>>(b3);

    // ---- readout ----
    pool_kernel<<<N_GRAPHS, 128>>>();
    final_kernel<<<N_GRAPHS, 64>>>(fc1_w, fc1_b, fc2_w, fc2_b, out);
}